// round 13
// baseline (speedup 1.0000x reference)
#include <cuda_runtime.h>
#include <cuda_fp16.h>
#include <math.h>
#include <stdint.h>

#define TX 160
#define TY 40
#define BB 16
#define HH 256
#define CC 512
#define INDIM 128
#define VV 30000
#define G4 1024
#define FF 896

#define NBLK 128
#define NTHR 320

// ---------------- device scratch ----------------
__device__ __align__(256) float g_pctx[TX * BB * CC];
__device__ __align__(256) uint32_t g_pctx_h2[TX * BB * 256];   // packed (c, c+256)
__device__ __align__(256) float g_gates[BB * G4];
__device__ __align__(256) float g_hq[BB * CC];
__device__ __align__(256) float g_acc[BB * TX];
__device__ __align__(256) float g_sc[BB * TX];
__device__ __align__(256) float g_atted[BB * CC];
__device__ __align__(256) float g_ifoc[BB * G4];
__device__ __align__(256) float g_feats[TY * BB * FF];
__device__ __align__(256) float g_logits[TY * BB * VV];
__device__ __align__(256) float g_cost[TY * BB];
__device__ __align__(256) float g_smax[TY * BB * 256];
__device__ __align__(256) float g_ssum[TY * BB * 256];
__device__ __align__(256) float g_tgt[TY * BB];
__device__ float g_rowM[BB], g_rowS[BB];
__device__ float g_cov_sum;
__device__ __align__(128) unsigned g_bar;
__device__ __align__(256) float g_SAb[TX * BB * CC];
__device__ __align__(256) float g_SAs[TX * BB * CC];
__device__ __align__(256) float g_SBb[VV * FF];
__device__ __align__(256) float g_SBs[VV * FF];

// ---------------- helpers ----------------
__device__ __forceinline__ float tanh_fast(float x) {
    float y;
    asm("tanh.approx.f32 %0, %1;" : "=f"(y) : "f"(x));
    return y;
}
__device__ __forceinline__ float sig_fast(float x) {
    return fmaf(tanh_fast(0.5f * x), 0.5f, 0.5f);
}
__device__ __forceinline__ float warp_sum(float s) {
#pragma unroll
    for (int o = 16; o > 0; o >>= 1) s += __shfl_xor_sync(0xffffffffu, s, o);
    return s;
}
__device__ __forceinline__ uint32_t pack_h2(float a, float b) {
    __half2 h = __floats2half2_rn(a, b);
    return *(uint32_t*)&h;
}

#define ACC_CHUNK(WPTR, XEXPR) { \
    float4 w = *(const float4*)(WPTR); \
    _Pragma("unroll") \
    for (int b = 0; b < 16; b++) { \
        float4 x = *(const float4*)(XEXPR); \
        acc[b] = fmaf(w.x, x.x, fmaf(w.y, x.y, fmaf(w.z, x.z, fmaf(w.w, x.w, acc[b])))); \
    } }

#define ALLRED16() { \
    _Pragma("unroll") \
    for (int o = 16; o > 0; o >>= 1) { \
        _Pragma("unroll") \
        for (int b = 0; b < 16; b++) acc[b] += __shfl_xor_sync(0xffffffffu, acc[b], o); \
    } }

__device__ __forceinline__ void grid_sync(unsigned& epoch) {
    __syncthreads();
    if (threadIdx.x == 0) {
        epoch += gridDim.x;
        asm volatile("red.release.gpu.global.add.u32 [%0], 1;" :: "l"(&g_bar) : "memory");
        unsigned v;
        while (true) {
            asm volatile("ld.acquire.gpu.global.u32 %0, [%1];" : "=r"(v) : "l"(&g_bar) : "memory");
            if (v >= epoch) break;
            __nanosleep(32);
        }
    }
    __syncthreads();
}

// ---------------- init ----------------
__global__ void init_kernel(const float* __restrict__ cov0) {
    int tid = threadIdx.x;
    if (tid == 0) { g_bar = 0u; g_cov_sum = 0.f; }
    for (int i = tid; i < BB * TX; i += blockDim.x) { g_acc[i] = cov0[i]; }
}

// ---------------- tf32 split ----------------
__device__ __forceinline__ void split_tf32(float v, float& hi, float& lo) {
    uint32_t bh;
    asm("cvt.rna.tf32.f32 %0, %1;" : "=r"(bh) : "f"(v));
    float fh = __uint_as_float(bh);
    float r = v - fh;
    uint32_t bl;
    asm("cvt.rna.tf32.f32 %0, %1;" : "=r"(bl) : "f"(r));
    hi = fh;
    lo = __uint_as_float(bl);
}

__global__ __launch_bounds__(256) void split_kernel(const float* __restrict__ src,
                                                    float* __restrict__ db,
                                                    float* __restrict__ ds, int n4) {
    int i = blockIdx.x * 256 + threadIdx.x;
    if (i < n4) {
        float4 v = ((const float4*)src)[i];
        float4 hb, lb;
        split_tf32(v.x, hb.x, lb.x);
        split_tf32(v.y, hb.y, lb.y);
        split_tf32(v.z, hb.z, lb.z);
        split_tf32(v.w, hb.w, lb.w);
        ((float4*)db)[i] = hb;
        ((float4*)ds)[i] = lb;
    }
}

// pack pctx to half2 (c, c+256) pairs
__global__ __launch_bounds__(256) void pack_pctx_kernel() {
    int idx = blockIdx.x * 256 + threadIdx.x;
    if (idx < TX * BB * 256) {
        int p = idx >> 8, c = idx & 255;
        g_pctx_h2[idx] = pack_h2(g_pctx[p * 512 + c], g_pctx[p * 512 + c + 256]);
    }
}

// ---------------- 3xTF32 GEMM, 2-stage cp.async (proven), optional fused softmax ----------------
__device__ __forceinline__ void mma_tf32(float* d, const uint32_t* a, const uint32_t* b) {
    asm volatile(
        "mma.sync.aligned.m16n8k8.row.col.f32.tf32.tf32.f32 "
        "{%0,%1,%2,%3}, {%4,%5,%6,%7}, {%8,%9}, {%0,%1,%2,%3};"
        : "+f"(d[0]), "+f"(d[1]), "+f"(d[2]), "+f"(d[3])
        : "r"(a[0]), "r"(a[1]), "r"(a[2]), "r"(a[3]), "r"(b[0]), "r"(b[1]));
}
__device__ __forceinline__ void cp_async16(uint32_t s, const void* g, int sz) {
    asm volatile("cp.async.cg.shared.global [%0], [%1], 16, %2;" :: "r"(s), "l"(g), "r"(sz));
}
#define CP_COMMIT() asm volatile("cp.async.commit_group;")

#define STG 16384
#define GEMM_SMEM (2 * STG * 4)
#define NEG_BIG (-1e30f)

__device__ __forceinline__ void sm_merge(float& M, float& S, float om, float os) {
    float nm = fmaxf(M, om);
    S = S * __expf(M - nm) + os * __expf(om - nm);
    M = nm;
}

__global__ __launch_bounds__(256, 1) void gemm_tf32_abT_bias(
    const float* __restrict__ Ab, const float* __restrict__ As,
    const float* __restrict__ Bb, const float* __restrict__ Bs,
    const float* __restrict__ bias, float* __restrict__ Cout,
    int M, int N, int K, const int* __restrict__ y_idx, int mode)
{
    extern __shared__ __align__(16) float sm[];
    const uint32_t smem_base = (uint32_t)__cvta_generic_to_shared(sm);

    const int tid = threadIdx.x;
    const int lane = tid & 31, wid = tid >> 5;
    const int g = lane >> 2, tig = lane & 3;
    const int wm = wid & 3, wn = wid >> 2;
    const int m0 = blockIdx.x * 128, n0 = blockIdx.y * 128;
    const int nt = K >> 5;

    const int s_row[4] = { (tid + 0) >> 3, (tid + 256) >> 3, (tid + 512) >> 3, (tid + 768) >> 3 };
    const int s_k4 = tid & 7;

    float acc[2][8][4];
#pragma unroll
    for (int mt = 0; mt < 2; mt++)
#pragma unroll
        for (int ntt = 0; ntt < 8; ntt++)
#pragma unroll
            for (int r = 0; r < 4; r++) acc[mt][ntt][r] = 0.f;

#define ISSUE_TILE(KT) { \
    int k0 = (KT) * 32; \
    uint32_t base = smem_base + ((KT) & 1) * (STG * 4); \
    _Pragma("unroll") \
    for (int i = 0; i < 4; i++) { \
        int row = s_row[i]; \
        uint32_t wb_ = (uint32_t)(row * 32 + ((s_k4 * 4) ^ ((row & 7) << 2))) * 4; \
        size_t offA = (size_t)(m0 + row) * K + k0 + s_k4 * 4; \
        cp_async16(base + wb_, Ab + offA, 16); \
        cp_async16(base + 4096 * 4 + wb_, As + offA, 16); \
        int gn = n0 + row; \
        int sz = (gn < N) ? 16 : 0; \
        size_t offB = (size_t)(gn < N ? gn : 0) * K + k0 + s_k4 * 4; \
        cp_async16(base + 8192 * 4 + wb_, Bb + offB, sz); \
        cp_async16(base + 12288 * 4 + wb_, Bs + offB, sz); \
    } \
    CP_COMMIT(); }

    ISSUE_TILE(0);

    for (int kt = 0; kt < nt; kt++) {
        if (kt + 1 < nt) {
            ISSUE_TILE(kt + 1);
            asm volatile("cp.async.wait_group 1;");
        } else {
            asm volatile("cp.async.wait_group 0;");
        }
        __syncthreads();

        const float* sAb = sm + (kt & 1) * STG;
        const float* sAs = sAb + 4096;
        const float* sBb = sAb + 8192;
        const float* sBs = sAb + 12288;
#pragma unroll
        for (int k8 = 0; k8 < 4; k8++) {
            const int kb = k8 * 8;
            uint32_t ab[2][4], as_[2][4];
#pragma unroll
            for (int mt = 0; mt < 2; mt++) {
                int r0 = wm * 32 + mt * 16 + g;
                int sw = (r0 & 7) << 2;
                int i0 = r0 * 32 + ((kb + tig) ^ sw);
                int i1 = r0 * 32 + ((kb + tig + 4) ^ sw);
                ab[mt][0] = __float_as_uint(sAb[i0]);
                ab[mt][1] = __float_as_uint(sAb[i0 + 256]);
                ab[mt][2] = __float_as_uint(sAb[i1]);
                ab[mt][3] = __float_as_uint(sAb[i1 + 256]);
                as_[mt][0] = __float_as_uint(sAs[i0]);
                as_[mt][1] = __float_as_uint(sAs[i0 + 256]);
                as_[mt][2] = __float_as_uint(sAs[i1]);
                as_[mt][3] = __float_as_uint(sAs[i1 + 256]);
            }
            uint32_t bb[8][2], bs[8][2];
#pragma unroll
            for (int ntt = 0; ntt < 8; ntt++) {
                int c0 = wn * 64 + ntt * 8 + g;
                int sw = (c0 & 7) << 2;
                int j0 = c0 * 32 + ((kb + tig) ^ sw);
                int j1 = c0 * 32 + ((kb + tig + 4) ^ sw);
                bb[ntt][0] = __float_as_uint(sBb[j0]);
                bb[ntt][1] = __float_as_uint(sBb[j1]);
                bs[ntt][0] = __float_as_uint(sBs[j0]);
                bs[ntt][1] = __float_as_uint(sBs[j1]);
            }
#pragma unroll
            for (int mt = 0; mt < 2; mt++)
#pragma unroll
                for (int ntt = 0; ntt < 8; ntt++) {
                    mma_tf32(acc[mt][ntt], ab[mt], bb[ntt]);
                    mma_tf32(acc[mt][ntt], ab[mt], bs[ntt]);
                    mma_tf32(acc[mt][ntt], as_[mt], bb[ntt]);
                }
        }
        __syncthreads();
    }
#undef ISSUE_TILE

    if (mode == 0) {
#pragma unroll
        for (int mt = 0; mt < 2; mt++) {
            int r0 = m0 + wm * 32 + mt * 16 + g;
#pragma unroll
            for (int ntt = 0; ntt < 8; ntt++) {
                int c = n0 + wn * 64 + ntt * 8 + tig * 2;
                if (c + 1 < N) {
                    float2 v0 = make_float2(acc[mt][ntt][0] + bias[c], acc[mt][ntt][1] + bias[c + 1]);
                    float2 v1 = make_float2(acc[mt][ntt][2] + bias[c], acc[mt][ntt][3] + bias[c + 1]);
                    *(float2*)&Cout[(size_t)r0 * N + c] = v0;
                    *(float2*)&Cout[(size_t)(r0 + 8) * N + c] = v1;
                } else if (c < N) {
                    Cout[(size_t)r0 * N + c] = acc[mt][ntt][0] + bias[c];
                    Cout[(size_t)(r0 + 8) * N + c] = acc[mt][ntt][2] + bias[c];
                }
            }
        }
        return;
    }

    // ---- fused softmax partials epilogue (logits mode) ----
    int row_g[4];
    int yi[4];
#pragma unroll
    for (int mt = 0; mt < 2; mt++)
#pragma unroll
        for (int h = 0; h < 2; h++) {
            row_g[mt * 2 + h] = m0 + wm * 32 + mt * 16 + g + h * 8;
            yi[mt * 2 + h] = y_idx[row_g[mt * 2 + h]];
        }

    float lmx[4] = {NEG_BIG, NEG_BIG, NEG_BIG, NEG_BIG};
    float lsm[4] = {0.f, 0.f, 0.f, 0.f};
#pragma unroll
    for (int mt = 0; mt < 2; mt++)
#pragma unroll
        for (int ntt = 0; ntt < 8; ntt++)
#pragma unroll
            for (int j = 0; j < 2; j++) {
                int col = n0 + wn * 64 + ntt * 8 + tig * 2 + j;
                if (col < N) {
                    float bz = bias[col];
                    lmx[mt * 2]     = fmaxf(lmx[mt * 2],     acc[mt][ntt][j] + bz);
                    lmx[mt * 2 + 1] = fmaxf(lmx[mt * 2 + 1], acc[mt][ntt][2 + j] + bz);
                }
            }
#pragma unroll
    for (int mt = 0; mt < 2; mt++)
#pragma unroll
        for (int ntt = 0; ntt < 8; ntt++)
#pragma unroll
            for (int j = 0; j < 2; j++) {
                int col = n0 + wn * 64 + ntt * 8 + tig * 2 + j;
                if (col < N) {
                    float bz = bias[col];
                    float v = acc[mt][ntt][j] + bz;
                    float w = acc[mt][ntt][2 + j] + bz;
                    lsm[mt * 2]     += __expf(v - lmx[mt * 2]);
                    lsm[mt * 2 + 1] += __expf(w - lmx[mt * 2 + 1]);
                    int r0 = row_g[mt * 2], r1 = row_g[mt * 2 + 1];
                    if (col == yi[mt * 2])     g_tgt[r0] = v;
                    if (col == yi[mt * 2 + 1]) g_tgt[r1] = w;
                    if (r0 >= (TY - 1) * BB) Cout[(size_t)r0 * N + col] = v;
                    if (r1 >= (TY - 1) * BB) Cout[(size_t)r1 * N + col] = w;
                }
            }
#pragma unroll
    for (int off = 1; off <= 2; off <<= 1) {
#pragma unroll
        for (int rdd = 0; rdd < 4; rdd++) {
            float om = __shfl_xor_sync(0xffffffffu, lmx[rdd], off);
            float os = __shfl_xor_sync(0xffffffffu, lsm[rdd], off);
            sm_merge(lmx[rdd], lsm[rdd], om, os);
        }
    }
    float* shm = sm;
    float* shs = sm + 256;
    __syncthreads();
    if (tig == 0) {
#pragma unroll
        for (int rdd = 0; rdd < 4; rdd++) {
            int row_local = row_g[rdd] - m0;
            shm[row_local * 2 + wn] = lmx[rdd];
            shs[row_local * 2 + wn] = lsm[rdd];
        }
    }
    __syncthreads();
    if (tid < 128) {
        float Mv = shm[tid * 2], Sv = shs[tid * 2];
        sm_merge(Mv, Sv, shm[tid * 2 + 1], shs[tid * 2 + 1]);
        g_smax[(size_t)(m0 + tid) * 256 + blockIdx.y] = Mv;
        g_ssum[(size_t)(m0 + tid) * 256 + blockIdx.y] = Sv;
    }
}

// merge per-row partials -> cost
__global__ __launch_bounds__(128) void merge_softmax_kernel(int nparts) {
    __shared__ float shm[128], shs[128];
    const int m = blockIdx.x;
    const int tid = threadIdx.x;
    float M = NEG_BIG, S = 0.f;
    for (int j = tid; j < nparts; j += 128)
        sm_merge(M, S, g_smax[(size_t)m * 256 + j], g_ssum[(size_t)m * 256 + j]);
    shm[tid] = M; shs[tid] = S; __syncthreads();
    for (int s = 64; s > 0; s >>= 1) {
        if (tid < s) {
            float Mv = shm[tid], Sv = shs[tid];
            sm_merge(Mv, Sv, shm[tid + s], shs[tid + s]);
            shm[tid] = Mv; shs[tid] = Sv;
        }
        __syncthreads();
    }
    if (tid == 0) {
        float Mv = shm[0], Sv = shs[0];
        g_cost[m] = Mv + logf(Sv) - g_tgt[m];
        if (m >= (TY - 1) * BB) {
            g_rowM[m - (TY - 1) * BB] = Mv;
            g_rowS[m - (TY - 1) * BB] = Sv;
        }
    }
}

__global__ __launch_bounds__(256) void ypred_kernel(float* __restrict__ out) {
    const int b = blockIdx.x;
    const int row = (TY - 1) * BB + b;
    const float Mv = g_rowM[b];
    const float inv = __fdividef(1.f, g_rowS[b]);
    for (int v = threadIdx.x; v < VV; v += 256)
        out[(size_t)b * VV + v] = __expf(g_logits[(size_t)row * VV + v] - Mv) * inv;
}

// ---------------- persistent recurrence ----------------
#define OFF_H     0
#define OFF_C     4096
#define OFF_H1    8192
#define OFF_C1    12288
#define OFF_WATT  16384
#define OFF_ATTP  16544
#define OFF_HQ2   16864
#define OFF_WCOV2 20960
#define OFF_UATT2 21216
#define SMEM_FLOATS 21472
#define SMEM_BYTES (SMEM_FLOATS * 4)

__global__ __launch_bounds__(NTHR, 1) void decoder_kernel(
    const float* __restrict__ y_emb, const float* __restrict__ context,
    const float* __restrict__ x_mask, const float* __restrict__ y_mask,
    const float* __restrict__ h0, const float* __restrict__ c0,
    const float* __restrict__ W_ih, const float* __restrict__ W_hh,
    const float* __restrict__ b_ih, const float* __restrict__ b_hh,
    const float* __restrict__ Wx, const float* __restrict__ Ux, const float* __restrict__ bx,
    const float* __restrict__ W_comb, const float* __restrict__ U_att,
    const float* __restrict__ W_cov)
{
    extern __shared__ __align__(16) float sh[];
    float* sh_h    = sh + OFF_H;
    float* sh_c    = sh + OFF_C;
    float* sh_h1   = sh + OFF_H1;
    float* sh_c1   = sh + OFF_C1;
    float* sh_watt = sh + OFF_WATT;
    float* sh_attp = sh + OFF_ATTP;
    uint32_t* sh_hq2   = (uint32_t*)(sh + OFF_HQ2);
    uint32_t* sh_wcov2 = (uint32_t*)(sh + OFF_WCOV2);
    uint32_t* sh_uatt2 = (uint32_t*)(sh + OFF_UATT2);

    const int tid = threadIdx.x;
    const int bk = blockIdx.x;
    const int lane = tid & 31;
    const int lwid = tid >> 5;
    const int myb = bk >> 3;
    const int sub = bk & 7;
    unsigned epoch = 0;

    for (int i = tid; i < BB * HH; i += NTHR) { sh_h[i] = h0[i]; sh_c[i] = c0[i]; }
    for (int i = tid; i < 256; i += NTHR) {
        sh_wcov2[i] = pack_h2(W_cov[i], W_cov[i + 256]);
        sh_uatt2[i] = pack_h2(U_att[i], U_att[i + 256]);
    }
    __syncthreads();

    for (int t = 0; t < TY; t++) {
        const float* yrow = y_emb + (size_t)t * BB * INDIM;

        // P1
        if (lwid < 8) {
            int j = lwid * NBLK + bk;
            float acc[16];
#pragma unroll
            for (int b = 0; b < 16; b++) acc[b] = 0.f;
            ACC_CHUNK(W_ih + (size_t)j * INDIM + lane * 4,     yrow + b * INDIM + lane * 4);
            ACC_CHUNK(W_hh + (size_t)j * HH + lane * 4,        sh_h + b * HH + lane * 4);
            ACC_CHUNK(W_hh + (size_t)j * HH + 128 + lane * 4,  sh_h + b * HH + 128 + lane * 4);
            ALLRED16();
            float bias = b_ih[j] + b_hh[j];
#pragma unroll
            for (int b = 0; b < 16; b++)
                if (lane == b) g_gates[b * G4 + j] = acc[b] + bias;
        }
        grid_sync(epoch);

        // P2
        for (int idx = tid; idx < BB * HH; idx += NTHR) {
            int b = idx >> 8, u = idx & 255;
            const float* gb = g_gates + b * G4 + u;
            float gi = gb[0], gf = gb[HH], gg = gb[2 * HH], go = gb[3 * HH];
            float c_old = sh_c[idx], h_old = sh_h[idx];
            float c1 = sig_fast(gf) * c_old + sig_fast(gi) * tanh_fast(gg);
            float h1 = sig_fast(go) * tanh_fast(c1);
            float ym = y_mask[t * BB + b];
            sh_h1[idx] = ym * h1 + (1.f - ym) * h_old;
            sh_c1[idx] = ym * c1 + (1.f - ym) * c_old;
        }
        __syncthreads();

        // P3
        if (lwid < 4) {
            int o = lwid * NBLK + bk;
            const float* wr = W_comb + (size_t)o * (2 * HH);
            float acc[16];
#pragma unroll
            for (int b = 0; b < 16; b++) acc[b] = 0.f;
            ACC_CHUNK(wr + lane * 4,        sh_h1 + b * HH + lane * 4);
            ACC_CHUNK(wr + 128 + lane * 4,  sh_h1 + b * HH + 128 + lane * 4);
            ACC_CHUNK(wr + 256 + lane * 4,  sh_c1 + b * HH + lane * 4);
            ACC_CHUNK(wr + 384 + lane * 4,  sh_c1 + b * HH + 128 + lane * 4);
            ALLRED16();
#pragma unroll
            for (int b = 0; b < 16; b++)
                if (lane == b) g_hq[b * CC + o] = acc[b];
        }
        grid_sync(epoch);

        // pack hq into smem half2 pairs
        for (int idx = tid; idx < BB * 256; idx += NTHR) {
            int b = idx >> 8, c = idx & 255;
            sh_hq2[idx] = pack_h2(g_hq[b * 512 + c], g_hq[b * 512 + c + 256]);
        }
        __syncthreads();

        // P4: all-half2 attention scores
#pragma unroll
        for (int r = 0; r < 2; r++) {
            int p = (r * 10 + lwid) * NBLK + bk;
            int x = p >> 4, b = p & 15;
            float accv = g_acc[b * TX + x];
            __half2 accv2 = __float2half2_rn(accv);
            const uint32_t* pch = g_pctx_h2 + (size_t)p * 256;
            const uint32_t* hqh = sh_hq2 + b * 256;
            float s = 0.f;
#pragma unroll
            for (int i = 0; i < 8; i++) {
                int c = i * 32 + lane;
                uint32_t pcu = pch[c];
                uint32_t hqu = hqh[c];
                uint32_t wcu = sh_wcov2[c];
                __half2 arg = __hfma2(accv2, *(__half2*)&wcu,
                                      __hadd2(*(__half2*)&pcu, *(__half2*)&hqu));
                uint32_t au = *(uint32_t*)&arg, tr;
                asm("tanh.approx.f16x2 %0, %1;" : "=r"(tr) : "r"(au));
                uint32_t uau = sh_uatt2[c];
                __half2 pr = __hmul2(*(__half2*)&tr, *(__half2*)&uau);
                float2 f = __half22float2(pr);
                s += f.x + f.y;
            }
            s = warp_sum(s);
            if (lane == 0) g_sc[b * TX + x] = x_mask[p] * s;
        }
        grid_sync(epoch);

        // P5a
        if (lwid == 0) {
            float v[5];
            float mx = -3.4e38f;
#pragma unroll
            for (int i = 0; i < 5; i++) {
                v[i] = g_sc[myb * TX + i * 32 + lane];
                mx = fmaxf(mx, v[i]);
            }
#pragma unroll
            for (int o = 16; o > 0; o >>= 1) mx = fmaxf(mx, __shfl_xor_sync(0xffffffffu, mx, o));
            float smv = 0.f;
#pragma unroll
            for (int i = 0; i < 5; i++) {
                v[i] = __expf(v[i] - mx) * x_mask[(i * 32 + lane) * BB + myb];
                smv += v[i];
            }
            smv = warp_sum(smv);
            float inv = __fdividef(1.f, smv);
#pragma unroll
            for (int i = 0; i < 5; i++) sh_watt[i * 32 + lane] = v[i] * inv;
        }
        __syncthreads();

        // P5b
        {
            int jid = sub * 10 + lwid;
            int cck = jid / 5, xck = jid % 5;
            int c = cck * 32 + lane;
            float s = 0.f;
#pragma unroll 8
            for (int i = 0; i < 32; i++) {
                int x = xck * 32 + i;
                s = fmaf(sh_watt[x], context[(size_t)(x * BB + myb) * CC + c], s);
            }
            sh_attp[(cck & 1) * 160 + xck * 32 + lane] = s;
        }
        __syncthreads();
        if (tid < 64) {
            int lc = tid >> 5, cl = tid & 31;
            const float* ap = sh_attp + lc * 160 + cl;
            float s = ap[0] + ap[32] + ap[64] + ap[96] + ap[128];
            g_atted[myb * CC + (2 * sub + lc) * 32 + cl] = s;
        }
        if (sub == 0 && lwid == 2) {
            float part = 0.f;
#pragma unroll
            for (int i = 0; i < 5; i++) {
                int x = i * 32 + lane;
                float w = sh_watt[x];
                float old = g_acc[myb * TX + x];
                part += fminf(w, old);
                g_acc[myb * TX + x] = old + w;
            }
            part = warp_sum(part);
            if (lane == 0) atomicAdd(&g_cov_sum, part);
        }
        grid_sync(epoch);

        // P6
        if (lwid < 8) {
            int j = lwid * NBLK + bk;
            float acc[16];
#pragma unroll
            for (int b = 0; b < 16; b++) acc[b] = 0.f;
            ACC_CHUNK(Ux + (size_t)j * HH + lane * 4,        sh_h1 + b * HH + lane * 4);
            ACC_CHUNK(Ux + (size_t)j * HH + 128 + lane * 4,  sh_h1 + b * HH + 128 + lane * 4);
#pragma unroll
            for (int cc = 0; cc < 4; cc++) {
                ACC_CHUNK(Wx + (size_t)j * CC + cc * 128 + lane * 4,
                          g_atted + b * CC + cc * 128 + lane * 4);
            }
            ALLRED16();
            float bias = bx[j];
#pragma unroll
            for (int b = 0; b < 16; b++)
                if (lane == b) g_ifoc[b * G4 + j] = acc[b] + bias;
        }
        grid_sync(epoch);

        // P7
        for (int idx = tid; idx < BB * HH; idx += NTHR) {
            int b = idx >> 8, u = idx & 255;
            const float* fb = g_ifoc + b * G4 + u;
            float i2 = fb[0], f2 = fb[HH], o2 = fb[2 * HH], g2 = fb[3 * HH];
            float c1 = sh_c1[idx], h1 = sh_h1[idx];
            float c2 = sig_fast(f2) * c1 + sig_fast(i2) * tanh_fast(g2);
            float h2 = sig_fast(o2) * tanh_fast(c2);
            float ym = y_mask[t * BB + b];
            c2 = ym * c2 + (1.f - ym) * c1;
            h2 = ym * h2 + (1.f - ym) * h1;
            sh_h[idx] = h2;
            sh_c[idx] = c2;
            g_feats[(size_t)(t * BB + b) * FF + u] = h2;
        }
        for (int idx2 = bk * NTHR + tid; idx2 < BB * (CC + INDIM); idx2 += NBLK * NTHR) {
            if (idx2 < BB * CC) {
                int b = idx2 >> 9, c = idx2 & 511;
                g_feats[(size_t)(t * BB + b) * FF + HH + c] = g_atted[idx2];
            } else {
                int q = idx2 - BB * CC;
                int b = q >> 7, kk = q & 127;
                g_feats[(size_t)(t * BB + b) * FF + HH + CC + kk] = yrow[b * INDIM + kk];
            }
        }
        __syncthreads();
    }
}

// ---------------- final scalars ----------------
__global__ void finalize_kernel(const float* __restrict__ y_mask, float* __restrict__ out) {
    int b = threadIdx.x;
    float cb = 0.f;
    if (b < BB) {
        float num = 0.f, den = 0.f;
        for (int t = 0; t < TY; t++) {
            float ym = y_mask[t * BB + b];
            num += g_cost[t * BB + b] * ym;
            den += ym;
        }
        cb = num / den;
    }
#pragma unroll
    for (int o = 16; o > 0; o >>= 1) cb += __shfl_xor_sync(0xffffffffu, cb, o);
    if (threadIdx.x == 0) {
        out[(size_t)BB * VV]     = cb / (float)BB;
        out[(size_t)BB * VV + 1] = g_cov_sum / (float)(TY * BB);
    }
}

// ---------------- launch ----------------
extern "C" void kernel_launch(void* const* d_in, const int* in_sizes, int n_in,
                              void* d_out, int out_size) {
    const float* y_emb   = (const float*)d_in[0];
    const float* context = (const float*)d_in[1];
    const float* h0      = (const float*)d_in[2];
    const float* c0      = (const float*)d_in[3];
    const float* x_mask  = (const float*)d_in[4];
    const float* y_mask  = (const float*)d_in[5];
    const float* cov0    = (const float*)d_in[6];
    const int*   y_idx   = (const int*)d_in[7];
    const float* W_ih    = (const float*)d_in[8];
    const float* W_hh    = (const float*)d_in[9];
    const float* b_ih    = (const float*)d_in[10];
    const float* b_hh    = (const float*)d_in[11];
    const float* Wx      = (const float*)d_in[12];
    const float* Ux      = (const float*)d_in[13];
    const float* bx      = (const float*)d_in[14];
    const float* Wc_att  = (const float*)d_in[15];
    const float* b_att   = (const float*)d_in[16];
    const float* W_comb  = (const float*)d_in[17];
    const float* U_att   = (const float*)d_in[18];
    const float* W_cov   = (const float*)d_in[19];
    const float* Wp      = (const float*)d_in[20];
    const float* bp      = (const float*)d_in[21];
    float* out = (float*)d_out;

    void *p_pctx, *p_feats, *p_logits, *p_ab, *p_as, *p_bb, *p_bs;
    cudaGetSymbolAddress(&p_pctx, g_pctx);
    cudaGetSymbolAddress(&p_feats, g_feats);
    cudaGetSymbolAddress(&p_logits, g_logits);
    cudaGetSymbolAddress(&p_ab, g_SAb);
    cudaGetSymbolAddress(&p_as, g_SAs);
    cudaGetSymbolAddress(&p_bb, g_SBb);
    cudaGetSymbolAddress(&p_bs, g_SBs);

    cudaFuncSetAttribute(decoder_kernel,
                         cudaFuncAttributeMaxDynamicSharedMemorySize, SMEM_BYTES);
    cudaFuncSetAttribute(gemm_tf32_abT_bias,
                         cudaFuncAttributeMaxDynamicSharedMemorySize, GEMM_SMEM);

    init_kernel<<<1, 256>>>(cov0);

    // pctx = context @ Wc_att^T + b_att
    {
        int nA = (TX * BB * CC) / 4, nB = (CC * CC) / 4;
        split_kernel<<<(nA + 255) / 256, 256>>>(context, (float*)p_ab, (float*)p_as, nA);
        split_kernel<<<(nB + 255) / 256, 256>>>(Wc_att, (float*)p_bb, (float*)p_bs, nB);
        dim3 grid((TX * BB) / 128, CC / 128);
        gemm_tf32_abT_bias<<<grid, 256, GEMM_SMEM>>>((const float*)p_ab, (const float*)p_as,
                                                     (const float*)p_bb, (const float*)p_bs,
                                                     b_att, (float*)p_pctx, TX * BB, CC, CC,
                                                     (const int*)0, 0);
        pack_pctx_kernel<<<(TX * BB * 256 + 255) / 256, 256>>>();
    }

    decoder_kernel<<<NBLK, NTHR, SMEM_BYTES>>>(y_emb, context, x_mask, y_mask,
                                               h0, c0,
                                               W_ih, W_hh, b_ih, b_hh, Wx, Ux, bx,
                                               W_comb, U_att, W_cov);

    // logits GEMM with fused softmax partials
    {
        int nA = (TY * BB * FF) / 4, nB = (VV * FF) / 4;
        split_kernel<<<(nA + 255) / 256, 256>>>((const float*)p_feats, (float*)p_ab, (float*)p_as, nA);
        split_kernel<<<(nB + 255) / 256, 256>>>(Wp, (float*)p_bb, (float*)p_bs, nB);
        dim3 grid((TY * BB) / 128, (VV + 127) / 128);   // (5, 235)
        gemm_tf32_abT_bias<<<grid, 256, GEMM_SMEM>>>((const float*)p_ab, (const float*)p_as,
                                                     (const float*)p_bb, (const float*)p_bs,
                                                     bp, (float*)p_logits, TY * BB, VV, FF,
                                                     y_idx, 1);
    }

    merge_softmax_kernel<<<TY * BB, 128>>>((VV + 127) / 128);
    ypred_kernel<<<BB, 256>>>(out);
    finalize_kernel<<<1, 32>>>(y_mask, out);
}

// round 15
// speedup vs baseline: 1.1484x; 1.1484x over previous
#include <cuda_runtime.h>
#include <cuda_fp16.h>
#include <cuda_bf16.h>
#include <math.h>
#include <stdint.h>

#define TX 160
#define TY 40
#define BB 16
#define HH 256
#define CC 512
#define INDIM 128
#define VV 30000
#define G4 1024
#define FF 896

#define NBLK 128
#define NTHR 320

// ---------------- device scratch ----------------
__device__ __align__(256) float g_pctx[TX * BB * CC];
__device__ __align__(256) uint32_t g_pctx_h2[TX * BB * 256];   // packed (c, c+256)
__device__ __align__(256) float g_gates[BB * G4];
__device__ __align__(256) float g_hq[BB * CC];
__device__ __align__(256) float g_acc[BB * TX];
__device__ __align__(256) float g_sc[BB * TX];
__device__ __align__(256) float g_atted[BB * CC];
__device__ __align__(256) float g_ifoc[BB * G4];
__device__ __align__(256) float g_feats[TY * BB * FF];
__device__ __align__(256) float g_logits[TY * BB * VV];
__device__ __align__(256) float g_cost[TY * BB];
__device__ __align__(256) float g_smax[TY * BB * 256];
__device__ __align__(256) float g_ssum[TY * BB * 256];
__device__ __align__(256) float g_tgt[TY * BB];
__device__ float g_rowM[BB], g_rowS[BB];
__device__ float g_cov_sum;
__device__ __align__(128) unsigned g_bar;
// bf16-split operand buffers (packed pairs along K; uint32 = 2 bf16)
__device__ __align__(256) uint32_t g_SAb[TX * BB * CC / 2];
__device__ __align__(256) uint32_t g_SAs[TX * BB * CC / 2];
__device__ __align__(256) uint32_t g_SBb[VV * FF / 2];
__device__ __align__(256) uint32_t g_SBs[VV * FF / 2];

// ---------------- helpers ----------------
__device__ __forceinline__ float tanh_fast(float x) {
    float y;
    asm("tanh.approx.f32 %0, %1;" : "=f"(y) : "f"(x));
    return y;
}
__device__ __forceinline__ float sig_fast(float x) {
    return fmaf(tanh_fast(0.5f * x), 0.5f, 0.5f);
}
__device__ __forceinline__ float warp_sum(float s) {
#pragma unroll
    for (int o = 16; o > 0; o >>= 1) s += __shfl_xor_sync(0xffffffffu, s, o);
    return s;
}
__device__ __forceinline__ uint32_t pack_h2(float a, float b) {
    __half2 h = __floats2half2_rn(a, b);
    return *(uint32_t*)&h;
}
__device__ __forceinline__ uint32_t pack_bf2(float lo, float hi) {
    __nv_bfloat162 h = __floats2bfloat162_rn(lo, hi);   // .x = lo half (lower k)
    return *(uint32_t*)&h;
}

#define ACC_CHUNK(WPTR, XEXPR) { \
    float4 w = *(const float4*)(WPTR); \
    _Pragma("unroll") \
    for (int b = 0; b < 16; b++) { \
        float4 x = *(const float4*)(XEXPR); \
        acc[b] = fmaf(w.x, x.x, fmaf(w.y, x.y, fmaf(w.z, x.z, fmaf(w.w, x.w, acc[b])))); \
    } }

#define ALLRED16() { \
    _Pragma("unroll") \
    for (int o = 16; o > 0; o >>= 1) { \
        _Pragma("unroll") \
        for (int b = 0; b < 16; b++) acc[b] += __shfl_xor_sync(0xffffffffu, acc[b], o); \
    } }

__device__ __forceinline__ void grid_sync(unsigned& epoch) {
    __syncthreads();
    if (threadIdx.x == 0) {
        epoch += gridDim.x;
        asm volatile("red.release.gpu.global.add.u32 [%0], 1;" :: "l"(&g_bar) : "memory");
        unsigned v;
        while (true) {
            asm volatile("ld.acquire.gpu.global.u32 %0, [%1];" : "=r"(v) : "l"(&g_bar) : "memory");
            if (v >= epoch) break;
            __nanosleep(32);
        }
    }
    __syncthreads();
}

// ---------------- init ----------------
__global__ void init_kernel(const float* __restrict__ cov0) {
    int tid = threadIdx.x;
    if (tid == 0) { g_bar = 0u; g_cov_sum = 0.f; }
    for (int i = tid; i < BB * TX; i += blockDim.x) { g_acc[i] = cov0[i]; }
}

// ---------------- bf16 split (hi + residual), packed pairs ----------------
__global__ __launch_bounds__(256) void split_bf16_kernel(const float* __restrict__ src,
                                                         uint32_t* __restrict__ db,
                                                         uint32_t* __restrict__ ds, int n4) {
    int i = blockIdx.x * 256 + threadIdx.x;
    if (i < n4) {
        float4 v = ((const float4*)src)[i];
        float hx = __bfloat162float(__float2bfloat16_rn(v.x));
        float hy = __bfloat162float(__float2bfloat16_rn(v.y));
        float hz = __bfloat162float(__float2bfloat16_rn(v.z));
        float hw = __bfloat162float(__float2bfloat16_rn(v.w));
        uint2 hb = make_uint2(pack_bf2(hx, hy), pack_bf2(hz, hw));
        uint2 lb = make_uint2(pack_bf2(v.x - hx, v.y - hy), pack_bf2(v.z - hz, v.w - hw));
        ((uint2*)db)[i] = hb;
        ((uint2*)ds)[i] = lb;
    }
}

// pack pctx to half2 (c, c+256) pairs
__global__ __launch_bounds__(256) void pack_pctx_kernel() {
    int idx = blockIdx.x * 256 + threadIdx.x;
    if (idx < TX * BB * 256) {
        int p = idx >> 8, c = idx & 255;
        g_pctx_h2[idx] = pack_h2(g_pctx[p * 512 + c], g_pctx[p * 512 + c + 256]);
    }
}

// ---------------- 3x-BF16 tensor GEMM, 2-stage cp.async, optional fused softmax ----------------
__device__ __forceinline__ void mma_bf16(float* d, const uint32_t* a, const uint32_t* b) {
    asm volatile(
        "mma.sync.aligned.m16n8k16.row.col.f32.bf16.bf16.f32 "
        "{%0,%1,%2,%3}, {%4,%5,%6,%7}, {%8,%9}, {%0,%1,%2,%3};"
        : "+f"(d[0]), "+f"(d[1]), "+f"(d[2]), "+f"(d[3])
        : "r"(a[0]), "r"(a[1]), "r"(a[2]), "r"(a[3]), "r"(b[0]), "r"(b[1]));
}
__device__ __forceinline__ void cp_async16(uint32_t s, const void* g, int sz) {
    asm volatile("cp.async.cg.shared.global [%0], [%1], 16, %2;" :: "r"(s), "l"(g), "r"(sz));
}
#define CP_COMMIT() asm volatile("cp.async.commit_group;")

// per-stage words: sAb 2048 | sAs 2048 | sBb 2048 | sBs 2048 = 8192 words (32KB)
#define STGW 8192
#define GEMM_SMEM (2 * STGW * 4)
#define NEG_BIG (-1e30f)

// swizzled word index within an 8KB tile: row 0..127, pair 0..15
__device__ __forceinline__ int swz(int row, int pair) {
    return row * 16 + (pair ^ (((row >> 1) & 3) << 2));
}

__device__ __forceinline__ void sm_merge(float& M, float& S, float om, float os) {
    float nm = fmaxf(M, om);
    S = S * __expf(M - nm) + os * __expf(om - nm);
    M = nm;
}

__global__ __launch_bounds__(256, 1) void gemm_bf16_abT_bias(
    const uint32_t* __restrict__ Ab, const uint32_t* __restrict__ As,
    const uint32_t* __restrict__ Bb, const uint32_t* __restrict__ Bs,
    const float* __restrict__ bias, float* __restrict__ Cout,
    int M, int N, int K, const int* __restrict__ y_idx, int mode)
{
    extern __shared__ __align__(16) uint32_t smu[];
    const uint32_t smem_base = (uint32_t)__cvta_generic_to_shared(smu);

    const int tid = threadIdx.x;
    const int lane = tid & 31, wid = tid >> 5;
    const int g = lane >> 2, tig = lane & 3;
    const int wm = wid & 3, wn = wid >> 2;
    const int m0 = blockIdx.x * 128, n0 = blockIdx.y * 128;
    const int Kp = K >> 1;                // uint32 pairs per row
    const int nt = K >> 5;                // 32-k tiles

    const int s_row[2] = { tid >> 2, (tid + 256) >> 2 };
    const int s_j = tid & 3;

    float acc[2][8][4];
#pragma unroll
    for (int mt = 0; mt < 2; mt++)
#pragma unroll
        for (int ntt = 0; ntt < 8; ntt++)
#pragma unroll
            for (int r = 0; r < 4; r++) acc[mt][ntt][r] = 0.f;

#define ISSUE_TILE(KT) { \
    int kp0 = (KT) * 16; \
    uint32_t base = smem_base + ((KT) & 1) * (STGW * 4); \
    _Pragma("unroll") \
    for (int i = 0; i < 2; i++) { \
        int row = s_row[i]; \
        uint32_t w4 = (uint32_t)swz(row, 4 * s_j) * 4; \
        size_t offA = (size_t)(m0 + row) * Kp + kp0 + 4 * s_j; \
        cp_async16(base + w4, Ab + offA, 16); \
        cp_async16(base + 2048 * 4 + w4, As + offA, 16); \
        int gn = n0 + row; \
        int sz = (gn < N) ? 16 : 0; \
        size_t offB = (size_t)(gn < N ? gn : 0) * Kp + kp0 + 4 * s_j; \
        cp_async16(base + 4096 * 4 + w4, Bb + offB, sz); \
        cp_async16(base + 6144 * 4 + w4, Bs + offB, sz); \
    } \
    CP_COMMIT(); }

    ISSUE_TILE(0);

    for (int kt = 0; kt < nt; kt++) {
        if (kt + 1 < nt) {
            ISSUE_TILE(kt + 1);
            asm volatile("cp.async.wait_group 1;");
        } else {
            asm volatile("cp.async.wait_group 0;");
        }
        __syncthreads();

        const uint32_t* sAb = smu + (kt & 1) * STGW;
        const uint32_t* sAs = sAb + 2048;
        const uint32_t* sBb = sAb + 4096;
        const uint32_t* sBs = sAb + 6144;
#pragma unroll
        for (int k16 = 0; k16 < 2; k16++) {
            const int kb2 = k16 * 8;       // pair offset of this k16 chunk
            uint32_t ab[2][4], as_[2][4];
#pragma unroll
            for (int mt = 0; mt < 2; mt++) {
                int r0 = wm * 32 + mt * 16 + g;
                int i00 = swz(r0,     kb2 + tig);
                int i10 = swz(r0 + 8, kb2 + tig);
                int i01 = swz(r0,     kb2 + tig + 4);
                int i11 = swz(r0 + 8, kb2 + tig + 4);
                ab[mt][0] = sAb[i00]; ab[mt][1] = sAb[i10];
                ab[mt][2] = sAb[i01]; ab[mt][3] = sAb[i11];
                as_[mt][0] = sAs[i00]; as_[mt][1] = sAs[i10];
                as_[mt][2] = sAs[i01]; as_[mt][3] = sAs[i11];
            }
            uint32_t bb[8][2], bs[8][2];
#pragma unroll
            for (int ntt = 0; ntt < 8; ntt++) {
                int c0 = wn * 64 + ntt * 8 + g;
                int j0 = swz(c0, kb2 + tig);
                int j1 = swz(c0, kb2 + tig + 4);
                bb[ntt][0] = sBb[j0]; bb[ntt][1] = sBb[j1];
                bs[ntt][0] = sBs[j0]; bs[ntt][1] = sBs[j1];
            }
#pragma unroll
            for (int mt = 0; mt < 2; mt++)
#pragma unroll
                for (int ntt = 0; ntt < 8; ntt++) {
                    mma_bf16(acc[mt][ntt], ab[mt], bb[ntt]);
                    mma_bf16(acc[mt][ntt], ab[mt], bs[ntt]);
                    mma_bf16(acc[mt][ntt], as_[mt], bb[ntt]);
                }
        }
        __syncthreads();
    }
#undef ISSUE_TILE

    if (mode == 0) {
#pragma unroll
        for (int mt = 0; mt < 2; mt++) {
            int r0 = m0 + wm * 32 + mt * 16 + g;
#pragma unroll
            for (int ntt = 0; ntt < 8; ntt++) {
                int c = n0 + wn * 64 + ntt * 8 + tig * 2;
                if (c + 1 < N) {
                    float2 v0 = make_float2(acc[mt][ntt][0] + bias[c], acc[mt][ntt][1] + bias[c + 1]);
                    float2 v1 = make_float2(acc[mt][ntt][2] + bias[c], acc[mt][ntt][3] + bias[c + 1]);
                    *(float2*)&Cout[(size_t)r0 * N + c] = v0;
                    *(float2*)&Cout[(size_t)(r0 + 8) * N + c] = v1;
                } else if (c < N) {
                    Cout[(size_t)r0 * N + c] = acc[mt][ntt][0] + bias[c];
                    Cout[(size_t)(r0 + 8) * N + c] = acc[mt][ntt][2] + bias[c];
                }
            }
        }
        return;
    }

    // ---- fused softmax partials epilogue (logits mode) ----
    int row_g[4];
    int yi[4];
#pragma unroll
    for (int mt = 0; mt < 2; mt++)
#pragma unroll
        for (int h = 0; h < 2; h++) {
            row_g[mt * 2 + h] = m0 + wm * 32 + mt * 16 + g + h * 8;
            yi[mt * 2 + h] = y_idx[row_g[mt * 2 + h]];
        }

    float lmx[4] = {NEG_BIG, NEG_BIG, NEG_BIG, NEG_BIG};
    float lsm[4] = {0.f, 0.f, 0.f, 0.f};
#pragma unroll
    for (int mt = 0; mt < 2; mt++)
#pragma unroll
        for (int ntt = 0; ntt < 8; ntt++)
#pragma unroll
            for (int j = 0; j < 2; j++) {
                int col = n0 + wn * 64 + ntt * 8 + tig * 2 + j;
                if (col < N) {
                    float bz = bias[col];
                    lmx[mt * 2]     = fmaxf(lmx[mt * 2],     acc[mt][ntt][j] + bz);
                    lmx[mt * 2 + 1] = fmaxf(lmx[mt * 2 + 1], acc[mt][ntt][2 + j] + bz);
                }
            }
#pragma unroll
    for (int mt = 0; mt < 2; mt++)
#pragma unroll
        for (int ntt = 0; ntt < 8; ntt++)
#pragma unroll
            for (int j = 0; j < 2; j++) {
                int col = n0 + wn * 64 + ntt * 8 + tig * 2 + j;
                if (col < N) {
                    float bz = bias[col];
                    float v = acc[mt][ntt][j] + bz;
                    float w = acc[mt][ntt][2 + j] + bz;
                    lsm[mt * 2]     += __expf(v - lmx[mt * 2]);
                    lsm[mt * 2 + 1] += __expf(w - lmx[mt * 2 + 1]);
                    int r0 = row_g[mt * 2], r1 = row_g[mt * 2 + 1];
                    if (col == yi[mt * 2])     g_tgt[r0] = v;
                    if (col == yi[mt * 2 + 1]) g_tgt[r1] = w;
                    if (r0 >= (TY - 1) * BB) Cout[(size_t)r0 * N + col] = v;
                    if (r1 >= (TY - 1) * BB) Cout[(size_t)r1 * N + col] = w;
                }
            }
#pragma unroll
    for (int off = 1; off <= 2; off <<= 1) {
#pragma unroll
        for (int rdd = 0; rdd < 4; rdd++) {
            float om = __shfl_xor_sync(0xffffffffu, lmx[rdd], off);
            float os = __shfl_xor_sync(0xffffffffu, lsm[rdd], off);
            sm_merge(lmx[rdd], lsm[rdd], om, os);
        }
    }
    float* shm = (float*)smu;
    float* shs = (float*)(smu + 256);
    __syncthreads();
    if (tig == 0) {
#pragma unroll
        for (int rdd = 0; rdd < 4; rdd++) {
            int row_local = row_g[rdd] - m0;
            shm[row_local * 2 + wn] = lmx[rdd];
            shs[row_local * 2 + wn] = lsm[rdd];
        }
    }
    __syncthreads();
    if (tid < 128) {
        float Mv = shm[tid * 2], Sv = shs[tid * 2];
        sm_merge(Mv, Sv, shm[tid * 2 + 1], shs[tid * 2 + 1]);
        g_smax[(size_t)(m0 + tid) * 256 + blockIdx.y] = Mv;
        g_ssum[(size_t)(m0 + tid) * 256 + blockIdx.y] = Sv;
    }
}

// merge per-row partials -> cost
__global__ __launch_bounds__(128) void merge_softmax_kernel(int nparts) {
    __shared__ float shm[128], shs[128];
    const int m = blockIdx.x;
    const int tid = threadIdx.x;
    float M = NEG_BIG, S = 0.f;
    for (int j = tid; j < nparts; j += 128)
        sm_merge(M, S, g_smax[(size_t)m * 256 + j], g_ssum[(size_t)m * 256 + j]);
    shm[tid] = M; shs[tid] = S; __syncthreads();
    for (int s = 64; s > 0; s >>= 1) {
        if (tid < s) {
            float Mv = shm[tid], Sv = shs[tid];
            sm_merge(Mv, Sv, shm[tid + s], shs[tid + s]);
            shm[tid] = Mv; shs[tid] = Sv;
        }
        __syncthreads();
    }
    if (tid == 0) {
        float Mv = shm[0], Sv = shs[0];
        g_cost[m] = Mv + logf(Sv) - g_tgt[m];
        if (m >= (TY - 1) * BB) {
            g_rowM[m - (TY - 1) * BB] = Mv;
            g_rowS[m - (TY - 1) * BB] = Sv;
        }
    }
}

__global__ __launch_bounds__(256) void ypred_kernel(float* __restrict__ out) {
    const int b = blockIdx.x;
    const int row = (TY - 1) * BB + b;
    const float Mv = g_rowM[b];
    const float inv = __fdividef(1.f, g_rowS[b]);
    for (int v = threadIdx.x; v < VV; v += 256)
        out[(size_t)b * VV + v] = __expf(g_logits[(size_t)row * VV + v] - Mv) * inv;
}

// ---------------- persistent recurrence (identical to round 13) ----------------
#define OFF_H     0
#define OFF_C     4096
#define OFF_H1    8192
#define OFF_C1    12288
#define OFF_WATT  16384
#define OFF_ATTP  16544
#define OFF_HQ2   16864
#define OFF_WCOV2 20960
#define OFF_UATT2 21216
#define SMEM_FLOATS 21472
#define SMEM_BYTES (SMEM_FLOATS * 4)

__global__ __launch_bounds__(NTHR, 1) void decoder_kernel(
    const float* __restrict__ y_emb, const float* __restrict__ context,
    const float* __restrict__ x_mask, const float* __restrict__ y_mask,
    const float* __restrict__ h0, const float* __restrict__ c0,
    const float* __restrict__ W_ih, const float* __restrict__ W_hh,
    const float* __restrict__ b_ih, const float* __restrict__ b_hh,
    const float* __restrict__ Wx, const float* __restrict__ Ux, const float* __restrict__ bx,
    const float* __restrict__ W_comb, const float* __restrict__ U_att,
    const float* __restrict__ W_cov)
{
    extern __shared__ __align__(16) float sh[];
    float* sh_h    = sh + OFF_H;
    float* sh_c    = sh + OFF_C;
    float* sh_h1   = sh + OFF_H1;
    float* sh_c1   = sh + OFF_C1;
    float* sh_watt = sh + OFF_WATT;
    float* sh_attp = sh + OFF_ATTP;
    uint32_t* sh_hq2   = (uint32_t*)(sh + OFF_HQ2);
    uint32_t* sh_wcov2 = (uint32_t*)(sh + OFF_WCOV2);
    uint32_t* sh_uatt2 = (uint32_t*)(sh + OFF_UATT2);

    const int tid = threadIdx.x;
    const int bk = blockIdx.x;
    const int lane = tid & 31;
    const int lwid = tid >> 5;
    const int myb = bk >> 3;
    const int sub = bk & 7;
    unsigned epoch = 0;

    for (int i = tid; i < BB * HH; i += NTHR) { sh_h[i] = h0[i]; sh_c[i] = c0[i]; }
    for (int i = tid; i < 256; i += NTHR) {
        sh_wcov2[i] = pack_h2(W_cov[i], W_cov[i + 256]);
        sh_uatt2[i] = pack_h2(U_att[i], U_att[i + 256]);
    }
    __syncthreads();

    for (int t = 0; t < TY; t++) {
        const float* yrow = y_emb + (size_t)t * BB * INDIM;

        // P1
        if (lwid < 8) {
            int j = lwid * NBLK + bk;
            float acc[16];
#pragma unroll
            for (int b = 0; b < 16; b++) acc[b] = 0.f;
            ACC_CHUNK(W_ih + (size_t)j * INDIM + lane * 4,     yrow + b * INDIM + lane * 4);
            ACC_CHUNK(W_hh + (size_t)j * HH + lane * 4,        sh_h + b * HH + lane * 4);
            ACC_CHUNK(W_hh + (size_t)j * HH + 128 + lane * 4,  sh_h + b * HH + 128 + lane * 4);
            ALLRED16();
            float bias = b_ih[j] + b_hh[j];
#pragma unroll
            for (int b = 0; b < 16; b++)
                if (lane == b) g_gates[b * G4 + j] = acc[b] + bias;
        }
        grid_sync(epoch);

        // P2
        for (int idx = tid; idx < BB * HH; idx += NTHR) {
            int b = idx >> 8, u = idx & 255;
            const float* gb = g_gates + b * G4 + u;
            float gi = gb[0], gf = gb[HH], gg = gb[2 * HH], go = gb[3 * HH];
            float c_old = sh_c[idx], h_old = sh_h[idx];
            float c1 = sig_fast(gf) * c_old + sig_fast(gi) * tanh_fast(gg);
            float h1 = sig_fast(go) * tanh_fast(c1);
            float ym = y_mask[t * BB + b];
            sh_h1[idx] = ym * h1 + (1.f - ym) * h_old;
            sh_c1[idx] = ym * c1 + (1.f - ym) * c_old;
        }
        __syncthreads();

        // P3
        if (lwid < 4) {
            int o = lwid * NBLK + bk;
            const float* wr = W_comb + (size_t)o * (2 * HH);
            float acc[16];
#pragma unroll
            for (int b = 0; b < 16; b++) acc[b] = 0.f;
            ACC_CHUNK(wr + lane * 4,        sh_h1 + b * HH + lane * 4);
            ACC_CHUNK(wr + 128 + lane * 4,  sh_h1 + b * HH + 128 + lane * 4);
            ACC_CHUNK(wr + 256 + lane * 4,  sh_c1 + b * HH + lane * 4);
            ACC_CHUNK(wr + 384 + lane * 4,  sh_c1 + b * HH + 128 + lane * 4);
            ALLRED16();
#pragma unroll
            for (int b = 0; b < 16; b++)
                if (lane == b) g_hq[b * CC + o] = acc[b];
        }
        grid_sync(epoch);

        // pack hq into smem half2 pairs
        for (int idx = tid; idx < BB * 256; idx += NTHR) {
            int b = idx >> 8, c = idx & 255;
            sh_hq2[idx] = pack_h2(g_hq[b * 512 + c], g_hq[b * 512 + c + 256]);
        }
        __syncthreads();

        // P4: all-half2 attention scores
#pragma unroll
        for (int r = 0; r < 2; r++) {
            int p = (r * 10 + lwid) * NBLK + bk;
            int x = p >> 4, b = p & 15;
            float accv = g_acc[b * TX + x];
            __half2 accv2 = __float2half2_rn(accv);
            const uint32_t* pch = g_pctx_h2 + (size_t)p * 256;
            const uint32_t* hqh = sh_hq2 + b * 256;
            float s = 0.f;
#pragma unroll
            for (int i = 0; i < 8; i++) {
                int c = i * 32 + lane;
                uint32_t pcu = pch[c];
                uint32_t hqu = hqh[c];
                uint32_t wcu = sh_wcov2[c];
                __half2 arg = __hfma2(accv2, *(__half2*)&wcu,
                                      __hadd2(*(__half2*)&pcu, *(__half2*)&hqu));
                uint32_t au = *(uint32_t*)&arg, tr;
                asm("tanh.approx.f16x2 %0, %1;" : "=r"(tr) : "r"(au));
                uint32_t uau = sh_uatt2[c];
                __half2 pr = __hmul2(*(__half2*)&tr, *(__half2*)&uau);
                float2 f = __half22float2(pr);
                s += f.x + f.y;
            }
            s = warp_sum(s);
            if (lane == 0) g_sc[b * TX + x] = x_mask[p] * s;
        }
        grid_sync(epoch);

        // P5a
        if (lwid == 0) {
            float v[5];
            float mx = -3.4e38f;
#pragma unroll
            for (int i = 0; i < 5; i++) {
                v[i] = g_sc[myb * TX + i * 32 + lane];
                mx = fmaxf(mx, v[i]);
            }
#pragma unroll
            for (int o = 16; o > 0; o >>= 1) mx = fmaxf(mx, __shfl_xor_sync(0xffffffffu, mx, o));
            float smv = 0.f;
#pragma unroll
            for (int i = 0; i < 5; i++) {
                v[i] = __expf(v[i] - mx) * x_mask[(i * 32 + lane) * BB + myb];
                smv += v[i];
            }
            smv = warp_sum(smv);
            float inv = __fdividef(1.f, smv);
#pragma unroll
            for (int i = 0; i < 5; i++) sh_watt[i * 32 + lane] = v[i] * inv;
        }
        __syncthreads();

        // P5b
        {
            int jid = sub * 10 + lwid;
            int cck = jid / 5, xck = jid % 5;
            int c = cck * 32 + lane;
            float s = 0.f;
#pragma unroll 8
            for (int i = 0; i < 32; i++) {
                int x = xck * 32 + i;
                s = fmaf(sh_watt[x], context[(size_t)(x * BB + myb) * CC + c], s);
            }
            sh_attp[(cck & 1) * 160 + xck * 32 + lane] = s;
        }
        __syncthreads();
        if (tid < 64) {
            int lc = tid >> 5, cl = tid & 31;
            const float* ap = sh_attp + lc * 160 + cl;
            float s = ap[0] + ap[32] + ap[64] + ap[96] + ap[128];
            g_atted[myb * CC + (2 * sub + lc) * 32 + cl] = s;
        }
        if (sub == 0 && lwid == 2) {
            float part = 0.f;
#pragma unroll
            for (int i = 0; i < 5; i++) {
                int x = i * 32 + lane;
                float w = sh_watt[x];
                float old = g_acc[myb * TX + x];
                part += fminf(w, old);
                g_acc[myb * TX + x] = old + w;
            }
            part = warp_sum(part);
            if (lane == 0) atomicAdd(&g_cov_sum, part);
        }
        grid_sync(epoch);

        // P6
        if (lwid < 8) {
            int j = lwid * NBLK + bk;
            float acc[16];
#pragma unroll
            for (int b = 0; b < 16; b++) acc[b] = 0.f;
            ACC_CHUNK(Ux + (size_t)j * HH + lane * 4,        sh_h1 + b * HH + lane * 4);
            ACC_CHUNK(Ux + (size_t)j * HH + 128 + lane * 4,  sh_h1 + b * HH + 128 + lane * 4);
#pragma unroll
            for (int cc = 0; cc < 4; cc++) {
                ACC_CHUNK(Wx + (size_t)j * CC + cc * 128 + lane * 4,
                          g_atted + b * CC + cc * 128 + lane * 4);
            }
            ALLRED16();
            float bias = bx[j];
#pragma unroll
            for (int b = 0; b < 16; b++)
                if (lane == b) g_ifoc[b * G4 + j] = acc[b] + bias;
        }
        grid_sync(epoch);

        // P7
        for (int idx = tid; idx < BB * HH; idx += NTHR) {
            int b = idx >> 8, u = idx & 255;
            const float* fb = g_ifoc + b * G4 + u;
            float i2 = fb[0], f2 = fb[HH], o2 = fb[2 * HH], g2 = fb[3 * HH];
            float c1 = sh_c1[idx], h1 = sh_h1[idx];
            float c2 = sig_fast(f2) * c1 + sig_fast(i2) * tanh_fast(g2);
            float h2 = sig_fast(o2) * tanh_fast(c2);
            float ym = y_mask[t * BB + b];
            c2 = ym * c2 + (1.f - ym) * c1;
            h2 = ym * h2 + (1.f - ym) * h1;
            sh_h[idx] = h2;
            sh_c[idx] = c2;
            g_feats[(size_t)(t * BB + b) * FF + u] = h2;
        }
        for (int idx2 = bk * NTHR + tid; idx2 < BB * (CC + INDIM); idx2 += NBLK * NTHR) {
            if (idx2 < BB * CC) {
                int b = idx2 >> 9, c = idx2 & 511;
                g_feats[(size_t)(t * BB + b) * FF + HH + c] = g_atted[idx2];
            } else {
                int q = idx2 - BB * CC;
                int b = q >> 7, kk = q & 127;
                g_feats[(size_t)(t * BB + b) * FF + HH + CC + kk] = yrow[b * INDIM + kk];
            }
        }
        __syncthreads();
    }
}

// ---------------- final scalars ----------------
__global__ void finalize_kernel(const float* __restrict__ y_mask, float* __restrict__ out) {
    int b = threadIdx.x;
    float cb = 0.f;
    if (b < BB) {
        float num = 0.f, den = 0.f;
        for (int t = 0; t < TY; t++) {
            float ym = y_mask[t * BB + b];
            num += g_cost[t * BB + b] * ym;
            den += ym;
        }
        cb = num / den;
    }
#pragma unroll
    for (int o = 16; o > 0; o >>= 1) cb += __shfl_xor_sync(0xffffffffu, cb, o);
    if (threadIdx.x == 0) {
        out[(size_t)BB * VV]     = cb / (float)BB;
        out[(size_t)BB * VV + 1] = g_cov_sum / (float)(TY * BB);
    }
}

// ---------------- launch ----------------
extern "C" void kernel_launch(void* const* d_in, const int* in_sizes, int n_in,
                              void* d_out, int out_size) {
    const float* y_emb   = (const float*)d_in[0];
    const float* context = (const float*)d_in[1];
    const float* h0      = (const float*)d_in[2];
    const float* c0      = (const float*)d_in[3];
    const float* x_mask  = (const float*)d_in[4];
    const float* y_mask  = (const float*)d_in[5];
    const float* cov0    = (const float*)d_in[6];
    const int*   y_idx   = (const int*)d_in[7];
    const float* W_ih    = (const float*)d_in[8];
    const float* W_hh    = (const float*)d_in[9];
    const float* b_ih    = (const float*)d_in[10];
    const float* b_hh    = (const float*)d_in[11];
    const float* Wx      = (const float*)d_in[12];
    const float* Ux      = (const float*)d_in[13];
    const float* bx      = (const float*)d_in[14];
    const float* Wc_att  = (const float*)d_in[15];
    const float* b_att   = (const float*)d_in[16];
    const float* W_comb  = (const float*)d_in[17];
    const float* U_att   = (const float*)d_in[18];
    const float* W_cov   = (const float*)d_in[19];
    const float* Wp      = (const float*)d_in[20];
    const float* bp      = (const float*)d_in[21];
    float* out = (float*)d_out;

    void *p_pctx, *p_feats, *p_logits, *p_ab, *p_as, *p_bb, *p_bs;
    cudaGetSymbolAddress(&p_pctx, g_pctx);
    cudaGetSymbolAddress(&p_feats, g_feats);
    cudaGetSymbolAddress(&p_logits, g_logits);
    cudaGetSymbolAddress(&p_ab, g_SAb);
    cudaGetSymbolAddress(&p_as, g_SAs);
    cudaGetSymbolAddress(&p_bb, g_SBb);
    cudaGetSymbolAddress(&p_bs, g_SBs);

    cudaFuncSetAttribute(decoder_kernel,
                         cudaFuncAttributeMaxDynamicSharedMemorySize, SMEM_BYTES);
    cudaFuncSetAttribute(gemm_bf16_abT_bias,
                         cudaFuncAttributeMaxDynamicSharedMemorySize, GEMM_SMEM);

    init_kernel<<<1, 256>>>(cov0);

    // pctx = context @ Wc_att^T + b_att
    {
        int nA = (TX * BB * CC) / 4, nB = (CC * CC) / 4;
        split_bf16_kernel<<<(nA + 255) / 256, 256>>>(context, (uint32_t*)p_ab, (uint32_t*)p_as, nA);
        split_bf16_kernel<<<(nB + 255) / 256, 256>>>(Wc_att, (uint32_t*)p_bb, (uint32_t*)p_bs, nB);
        dim3 grid((TX * BB) / 128, CC / 128);
        gemm_bf16_abT_bias<<<grid, 256, GEMM_SMEM>>>((const uint32_t*)p_ab, (const uint32_t*)p_as,
                                                     (const uint32_t*)p_bb, (const uint32_t*)p_bs,
                                                     b_att, (float*)p_pctx, TX * BB, CC, CC,
                                                     (const int*)0, 0);
        pack_pctx_kernel<<<(TX * BB * 256 + 255) / 256, 256>>>();
    }

    decoder_kernel<<<NBLK, NTHR, SMEM_BYTES>>>(y_emb, context, x_mask, y_mask,
                                               h0, c0,
                                               W_ih, W_hh, b_ih, b_hh, Wx, Ux, bx,
                                               W_comb, U_att, W_cov);

    // logits GEMM with fused softmax partials
    {
        int nA = (TY * BB * FF) / 4, nB = (VV * FF) / 4;
        split_bf16_kernel<<<(nA + 255) / 256, 256>>>((const float*)p_feats, (uint32_t*)p_ab, (uint32_t*)p_as, nA);
        split_bf16_kernel<<<(nB + 255) / 256, 256>>>(Wp, (uint32_t*)p_bb, (uint32_t*)p_bs, nB);
        dim3 grid((TY * BB) / 128, (VV + 127) / 128);   // (5, 235)
        gemm_bf16_abT_bias<<<grid, 256, GEMM_SMEM>>>((const uint32_t*)p_ab, (const uint32_t*)p_as,
                                                     (const uint32_t*)p_bb, (const uint32_t*)p_bs,
                                                     bp, (float*)p_logits, TY * BB, VV, FF,
                                                     y_idx, 1);
    }

    merge_softmax_kernel<<<TY * BB, 128>>>((VV + 127) / 128);
    ypred_kernel<<<BB, 256>>>(out);
    finalize_kernel<<<1, 32>>>(y_mask, out);
}